// round 14
// baseline (speedup 1.0000x reference)
#include <cuda_runtime.h>

// ---------------------------------------------------------------------------
// GAT attention aggregation, sm_103a — CSR-gather, atomic-free placement.
//   x:          [50000, 128] f32      (d_in[0])
//   edge_index: [2, 600000]  i32      (d_in[1])  row0=src, row1=dst
//   att:        [8, 32]      f32      (d_in[2])  [:,:16]=a_src, [:,16:]=a_dst
//   out:        [50000, 128] f32
//
// Pipeline (5 launches):
//   k_scores_hist : per-(node,head) scores s_src,s_dst + dst-degree histogram;
//                   the histogram atomicAdd's RETURN VALUE is each edge's rank
//                   within its dst segment -> saved to g_rank (free).
//   k_scan1/2     : 196-block exclusive scan of degrees -> g_offs
//   k_edge_place  : NO ATOMICS: pos = offs[dst] + rank[e]; all loads
//                   independent (ei, rank, offs, 4x16B score rows) -> MLP ~7;
//                   writes src + w[8] = exp(lrelu(ssrc[src]+sdst[dst])) at pos.
//   k_gather      : warp per node, 4x unrolled; acc += w*x[src];
//                   out = acc/sum(w); zeroes g_deg[n] for next replay.
//
// No softmax max-shift: logits ~N(0,5.7^2) << 88, exp() safe in fp32, ratio
// identical (validated rel_err ~2.4e-7 across R7-R13).
// ---------------------------------------------------------------------------

#define N_NODES 50000
#define N_EDGES 600000
#define CH      128
#define HEADS   8
#define HD      16
#define NBLK    ((N_NODES + 255) / 256)              // 196

#define SCORE_BLKS ((N_NODES * HEADS + 255) / 256)   // 1563
#define HIST_BLKS  ((N_EDGES / 2 + 255) / 256)       // 1172 (2 edges/thread)

// Scratch (__device__ globals; no allocation allowed). ~25 MB total.
__device__ float g_ssrc[N_NODES * HEADS];
__device__ float g_sdst[N_NODES * HEADS];
__device__ int   g_deg[N_NODES];                 // zero-init; re-zeroed by k_gather
__device__ int   g_offs[N_NODES];
__device__ int   g_rank[N_EDGES];                // edge's arrival rank within dst
__device__ int   g_bsum[NBLK];
__device__ int   g_csrc[N_EDGES];                // CSR-ordered source ids
__device__ float g_wcsr[(size_t)N_EDGES * HEADS];// CSR-ordered exp-weights

// ---------------------------------------------------------------------------
// Blocks [0, SCORE_BLKS): per-(node,head) score dots.
// Blocks [SCORE_BLKS, ...): dst histogram (2 edges/thread) + rank capture.
__global__ void k_scores_hist(const float* __restrict__ x,
                              const float* __restrict__ att,
                              const int* __restrict__ ei) {
    int b = blockIdx.x;
    if (b < SCORE_BLKS) {
        int i = b * 256 + threadIdx.x;
        if (i >= N_NODES * HEADS) return;
        int n = i >> 3, h = i & 7;
        const float4* xr = (const float4*)(x + (size_t)n * CH + h * HD);
        const float4* as = (const float4*)(att + h * 2 * HD);
        const float4* ad = (const float4*)(att + h * 2 * HD + HD);
        float s = 0.f, t = 0.f;
#pragma unroll
        for (int j = 0; j < 4; j++) {
            float4 xv = xr[j], av = as[j], dv = ad[j];
            s += xv.x * av.x + xv.y * av.y + xv.z * av.z + xv.w * av.w;
            t += xv.x * dv.x + xv.y * dv.y + xv.z * dv.z + xv.w * dv.w;
        }
        g_ssrc[i] = s;
        g_sdst[i] = t;
    } else {
        int t2 = (b - SCORE_BLKS) * 256 + threadIdx.x;
        if (t2 < N_EDGES / 2) {
            int2 dd = ((const int2*)(ei + N_EDGES))[t2];
            int r0 = atomicAdd(&g_deg[dd.x], 1);     // return value = rank: free
            int r1 = atomicAdd(&g_deg[dd.y], 1);
            ((int2*)g_rank)[t2] = make_int2(r0, r1); // stream store
        }
    }
}

// 196-block local exclusive scan; emit per-block totals.
__global__ void k_scan1() {
    __shared__ int sh[256];
    int t = threadIdx.x;
    int i = blockIdx.x * 256 + t;
    int v = (i < N_NODES) ? g_deg[i] : 0;
    sh[t] = v;
    __syncthreads();
#pragma unroll
    for (int off = 1; off < 256; off <<= 1) {
        int add = (t >= off) ? sh[t - off] : 0;
        __syncthreads();
        sh[t] += add;
        __syncthreads();
    }
    if (i < N_NODES) g_offs[i] = sh[t] - v;          // exclusive within block
    if (t == 255) g_bsum[blockIdx.x] = sh[255];
}

// Each block reduces preceding block sums -> base, applies it.
__global__ void k_scan2() {
    __shared__ int sh[256];
    int t = threadIdx.x;
    int bid = blockIdx.x;
    sh[t] = (t < NBLK && t < bid) ? g_bsum[t] : 0;
    __syncthreads();
#pragma unroll
    for (int off = 128; off > 0; off >>= 1) {
        if (t < off) sh[t] += sh[t + off];
        __syncthreads();
    }
    int base = sh[0];
    int i = bid * 256 + t;
    if (i < N_NODES) g_offs[i] += base;
}

// Atomic-free placement: pos = offs[dst] + rank[e]. All loads independent.
__global__ void k_edge_place(const int* __restrict__ ei) {
    int e = blockIdx.x * blockDim.x + threadIdx.x;
    if (e >= N_EDGES) return;
    int s    = __ldg(ei + e);
    int d    = __ldg(ei + N_EDGES + e);
    int rank = __ldg(g_rank + e);
    // offs gather + 4 score-row loads all issue back-to-back (no RMW chain)
    int base = __ldg(g_offs + d);
    const float4* ps = (const float4*)(g_ssrc + s * HEADS);
    const float4* pd = (const float4*)(g_sdst + d * HEADS);
    float4 s0 = ps[0], s1 = ps[1], d0 = pd[0], d1 = pd[1];

    float a[8] = { s0.x + d0.x, s0.y + d0.y, s0.z + d0.z, s0.w + d0.w,
                   s1.x + d1.x, s1.y + d1.y, s1.z + d1.z, s1.w + d1.w };
    float w[8];
#pragma unroll
    for (int h = 0; h < 8; h++) {
        float v = a[h] >= 0.f ? a[h] : 0.2f * a[h];
        w[h] = __expf(v);
    }
    int pos = base + rank;
    g_csrc[pos] = s;
    float4* pw = (float4*)(g_wcsr + (size_t)pos * HEADS);
    pw[0] = make_float4(w[0], w[1], w[2], w[3]);
    pw[1] = make_float4(w[4], w[5], w[6], w[7]);
}

// One warp per node, 4x unrolled. Lane covers 4 channels; head = lane/4.
// src/w stream sequentially; only x[src] rows are random (512B/warp, full lines).
__global__ void k_gather(const float* __restrict__ x, float* __restrict__ out) {
    int gid = blockIdx.x * blockDim.x + threadIdx.x;
    int n = gid >> 5, lane = gid & 31;
    if (n >= N_NODES) return;
    int start = g_offs[n];
    int cnt   = g_deg[n];
    int h = lane >> 2;
    float4 acc = make_float4(0.f, 0.f, 0.f, 0.f);
    float sum = 0.f;
    int k = 0;
    for (; k + 4 <= cnt; k += 4) {
        int p = start + k;
        int s0 = g_csrc[p],     s1 = g_csrc[p + 1];
        int s2 = g_csrc[p + 2], s3 = g_csrc[p + 3];
        float w0 = g_wcsr[(size_t)p * HEADS + h];
        float w1 = g_wcsr[(size_t)(p + 1) * HEADS + h];
        float w2 = g_wcsr[(size_t)(p + 2) * HEADS + h];
        float w3 = g_wcsr[(size_t)(p + 3) * HEADS + h];
        float4 x0 = ((const float4*)(x + (size_t)s0 * CH))[lane];
        float4 x1 = ((const float4*)(x + (size_t)s1 * CH))[lane];
        float4 x2 = ((const float4*)(x + (size_t)s2 * CH))[lane];
        float4 x3 = ((const float4*)(x + (size_t)s3 * CH))[lane];
        acc.x += w0 * x0.x; acc.y += w0 * x0.y; acc.z += w0 * x0.z; acc.w += w0 * x0.w;
        acc.x += w1 * x1.x; acc.y += w1 * x1.y; acc.z += w1 * x1.z; acc.w += w1 * x1.w;
        acc.x += w2 * x2.x; acc.y += w2 * x2.y; acc.z += w2 * x2.z; acc.w += w2 * x2.w;
        acc.x += w3 * x3.x; acc.y += w3 * x3.y; acc.z += w3 * x3.z; acc.w += w3 * x3.w;
        sum += w0 + w1 + w2 + w3;
    }
    for (; k < cnt; k++) {
        int p = start + k;
        int s0 = g_csrc[p];
        float w0 = g_wcsr[(size_t)p * HEADS + h];
        float4 x0 = ((const float4*)(x + (size_t)s0 * CH))[lane];
        acc.x += w0 * x0.x; acc.y += w0 * x0.y; acc.z += w0 * x0.z; acc.w += w0 * x0.w;
        sum += w0;
    }
    if (lane == 0) g_deg[n] = 0;                     // ready for next replay
    float r = 1.f / fmaxf(sum, 1e-10f);
    ((float4*)(out + (size_t)n * CH))[lane] =
        make_float4(acc.x * r, acc.y * r, acc.z * r, acc.w * r);
}

// ---------------------------------------------------------------------------
extern "C" void kernel_launch(void* const* d_in, const int* in_sizes, int n_in,
                              void* d_out, int out_size) {
    const float* x   = (const float*)d_in[0];
    const int*   ei  = (const int*)d_in[1];
    const float* att = (const float*)d_in[2];
    float*       out = (float*)d_out;

    k_scores_hist<<<SCORE_BLKS + HIST_BLKS, 256>>>(x, att, ei);
    k_scan1<<<NBLK, 256>>>();
    k_scan2<<<NBLK, 256>>>();
    k_edge_place<<<(N_EDGES + 255) / 256, 256>>>(ei);
    k_gather<<<((size_t)N_NODES * 32 + 255) / 256, 256>>>(x, out);
}